// round 11
// baseline (speedup 1.0000x reference)
#include <cuda_runtime.h>
#include <cstdint>

#define K_DIM 8192
#define M_DIM 8192

#define SCAP 128
#define BAND_CAP (1024 * 1024)
#define GEMV2_SMEM (128 * 132 * 4)     // 67584 B: x int8, padded 132-word pitch per g64

typedef unsigned long long ull;

// ---------------- static device scratch ----------------
__device__ float4 g_xt4[K_DIM * 2];            // x_hat fp32 transposed [K][8] (for correction)
__device__ unsigned g_xs[2048 * 8];            // x int8 scrambled [g4][n] (64 KB)
__device__ float g_sc[128 * 8];                // act scales [g64][n]
__device__ unsigned char g_code[(size_t)M_DIM * K_DIM / 4];  // 2-bit codes, row-major (16 MB)
__device__ float g_ssum[256];                  // sample partials
__device__ float g_bsum[1024];                 // exact |W| partials
__device__ float g_tlo, g_thi;                 // conservative band bounds
__device__ float g_thresh, g_wdeq;             // exact threshold, dequant
__device__ unsigned g_bandcnt;
__device__ uint2 g_band[BAND_CAP];             // (row*8192+k, bits(w))
__device__ float g_corr[M_DIM * 8];            // correction accumulators
__device__ float g_part2[M_DIM * 8];           // gemv2 output [row][n]
__device__ unsigned g_doneS = 0, g_doneP = 0;  // last-block counters

// ---------------- kernel 1: sample first 16 MB -> t-hat band bounds ----------------
__global__ void sample_kernel(const float4* __restrict__ W4) {
    __shared__ float sm[8];
    __shared__ bool amLast;
    int tid = threadIdx.x, lane = tid & 31, w = tid >> 5;
    int t0 = blockIdx.x * 256 + tid;
    const int stride = 256 * 256;
    float s = 0.f;
#pragma unroll 4
    for (int it = 0; it < 16; it++) {
        float4 v = __ldg(W4 + t0 + (size_t)it * stride);
        s += fabsf(v.x) + fabsf(v.y) + fabsf(v.z) + fabsf(v.w);
    }
#pragma unroll
    for (int off = 16; off; off >>= 1) s += __shfl_xor_sync(0xffffffffu, s, off);
    if (lane == 0) sm[w] = s;
    __syncthreads();
    if (tid == 0) g_ssum[blockIdx.x] = sm[0] + sm[1] + sm[2] + sm[3] + sm[4] + sm[5] + sm[6] + sm[7];
    __syncthreads();
    if (tid == 0) {
        __threadfence();
        amLast = (atomicAdd(&g_doneS, 1u) == 255u);
    }
    __syncthreads();
    if (amLast) {
        __threadfence();
        float t = g_ssum[tid];
#pragma unroll
        for (int off = 16; off; off >>= 1) t += __shfl_xor_sync(0xffffffffu, t, off);
        __syncthreads();
        if (lane == 0) sm[w] = t;
        __syncthreads();
        if (tid == 0) {
            float tot = 0.f;
#pragma unroll
            for (int i = 0; i < 8; i++) tot += sm[i];
            float mean_s = tot * (1.0f / 4194304.0f);
            float t_hat = 0.5f * fmaxf(mean_s, 1e-5f);
            g_tlo = t_hat * 0.998f;
            g_thi = t_hat * 1.002f;
            g_bandcnt = 0u;
            g_doneS = 0u;
        }
    }
}

// ---------------- kernel 2: prep ----------------
// blocks 0-1023: exact |W| sums (BIT-EXACT order) + 2-bit code gen + band capture
// blocks 1024-1151: activation quant (fp x_hat + int8 scrambled + scales) + zero corr
// last block: exact mean -> exact threshold
__global__ void prep_kernel(const float* __restrict__ x, const float4* __restrict__ W4) {
    __shared__ float sm[8];
    __shared__ bool amLast;
    __shared__ uint2 s_band[SCAP];
    __shared__ int s_cnt;
    __shared__ unsigned s_gbase;
    int tid = threadIdx.x, lane = tid & 31, w = tid >> 5;
    if (tid == 0) s_cnt = 0;
    __syncthreads();

    if (blockIdx.x < 1024) {
        const float thi = g_thi, tlo = g_tlo;
        const int stride = 1024 * 256;
        unsigned t0 = blockIdx.x * 256 + tid;
        const float4* p = W4 + t0;

        auto push = [&](unsigned eidx, float v) {
            int slot = atomicAdd(&s_cnt, 1);
            uint2 ent = make_uint2(eidx, __float_as_uint(v));
            if (slot < SCAP) s_band[slot] = ent;
            else {
                unsigned gp = atomicAdd(&g_bandcnt, 1u);
                if (gp < BAND_CAP) g_band[gp] = ent;
            }
        };
        auto cg = [&](float4 v, unsigned fi) {
            float a0 = fabsf(v.x), a1 = fabsf(v.y), a2 = fabsf(v.z), a3 = fabsf(v.w);
            bool p0 = a0 > thi, p1 = a1 > thi, p2 = a2 > thi, p3 = a3 > thi;
            unsigned c0 = p0 ? (1u | ((__float_as_uint(v.x) >> 30) & 2u)) : 0u;
            unsigned c1 = p1 ? (1u | ((__float_as_uint(v.y) >> 30) & 2u)) : 0u;
            unsigned c2 = p2 ? (1u | ((__float_as_uint(v.z) >> 30) & 2u)) : 0u;
            unsigned c3 = p3 ? (1u | ((__float_as_uint(v.w) >> 30) & 2u)) : 0u;
            g_code[fi] = (unsigned char)(c0 | (c1 << 2) | (c2 << 4) | (c3 << 6));
            float m0 = p0 ? 0.f : a0, m1 = p1 ? 0.f : a1;
            float m2 = p2 ? 0.f : a2, m3 = p3 ? 0.f : a3;
            if (fmaxf(fmaxf(m0, m1), fmaxf(m2, m3)) > tlo) {   // rare
                if (!p0 && a0 > tlo) push(fi * 4 + 0, v.x);
                if (!p1 && a1 > tlo) push(fi * 4 + 1, v.y);
                if (!p2 && a2 > tlo) push(fi * 4 + 2, v.z);
                if (!p3 && a3 > tlo) push(fi * 4 + 3, v.w);
            }
        };

        float s = 0.f;
#pragma unroll 2
        for (int it = 0; it < 64; it += 4) {
            float4 a = __ldg(p + (size_t)(it + 0) * stride);
            float4 b = __ldg(p + (size_t)(it + 1) * stride);
            float4 c = __ldg(p + (size_t)(it + 2) * stride);
            float4 d = __ldg(p + (size_t)(it + 3) * stride);
            s += fabsf(a.x) + fabsf(a.y) + fabsf(a.z) + fabsf(a.w);
            s += fabsf(b.x) + fabsf(b.y) + fabsf(b.z) + fabsf(b.w);
            s += fabsf(c.x) + fabsf(c.y) + fabsf(c.z) + fabsf(c.w);
            s += fabsf(d.x) + fabsf(d.y) + fabsf(d.z) + fabsf(d.w);
            cg(a, t0 + (unsigned)(it + 0) * stride);
            cg(b, t0 + (unsigned)(it + 1) * stride);
            cg(c, t0 + (unsigned)(it + 2) * stride);
            cg(d, t0 + (unsigned)(it + 3) * stride);
        }
#pragma unroll
        for (int off = 16; off; off >>= 1) s += __shfl_xor_sync(0xffffffffu, s, off);
        if (lane == 0) sm[w] = s;
        __syncthreads();
        if (tid == 0) {
            float tot = 0.f;
#pragma unroll
            for (int i = 0; i < 8; i++) tot += sm[i];
            g_bsum[blockIdx.x] = tot;
            int cnt = s_cnt; if (cnt > SCAP) cnt = SCAP;
            s_gbase = atomicAdd(&g_bandcnt, (unsigned)cnt);
        }
        __syncthreads();
        int cnt = s_cnt; if (cnt > SCAP) cnt = SCAP;
        for (int i = tid; i < cnt; i += 256) {
            unsigned gp = s_gbase + (unsigned)i;
            if (gp < BAND_CAP) g_band[gp] = s_band[i];
        }
    } else {
        // --- activation quant: fp x_hat + int8 scrambled + scales; zero corr ---
        int gid = (blockIdx.x - 1024) * 256 + tid;   // 0..32767
        g_corr[gid] = 0.f;
        g_corr[gid + 32768] = 0.f;
        int gw = gid >> 5;
        int n = gw >> 7;
        int g = gw & 127;
        int k0 = g * 64 + lane;
        float a = x[n * K_DIM + k0];
        float b = x[n * K_DIM + k0 + 32];
        float mx = fmaxf(fabsf(a), fabsf(b));
#pragma unroll
        for (int off = 16; off; off >>= 1)
            mx = fmaxf(mx, __shfl_xor_sync(0xffffffffu, mx, off));
        float sc = fmaxf(__fdiv_rn(mx, 127.0f), 1e-8f);
        float ra = rintf(__fdiv_rn(a, sc));
        float rb = rintf(__fdiv_rn(b, sc));
        float ah = ra * sc, bh = rb * sc;
        float* xt = (float*)g_xt4;
        xt[k0 * 8 + n] = ah;
        xt[(k0 + 32) * 8 + n] = bh;
        // int8 scrambled: word[(k>>2)*8 + n], byte pos = bitrev2(k&3)  {0:0,1:2,2:1,3:3}
        signed char* xs8 = (signed char*)g_xs;
        int r = k0 & 3;
        int pos = ((r & 1) << 1) | ((r >> 1) & 1);
        xs8[((k0 >> 2) * 8 + n) * 4 + pos] = (signed char)(int)ra;
        int k1 = k0 + 32, r1 = k1 & 3;
        int pos1 = ((r1 & 1) << 1) | ((r1 >> 1) & 1);
        xs8[((k1 >> 2) * 8 + n) * 4 + pos1] = (signed char)(int)rb;
        if (lane == 0) g_sc[g * 8 + n] = sc;
        __syncthreads();   // symmetric before counter
    }

    if (tid == 0) {
        __threadfence();
        amLast = (atomicAdd(&g_doneP, 1u) == 1151u);
    }
    __syncthreads();
    if (amLast) {
        __threadfence();
        float s = g_bsum[tid] + g_bsum[tid + 256] + g_bsum[tid + 512] + g_bsum[tid + 768];
#pragma unroll
        for (int off = 16; off; off >>= 1) s += __shfl_xor_sync(0xffffffffu, s, off);
        __syncthreads();
        if (lane == 0) sm[w] = s;
        __syncthreads();
        if (tid == 0) {
            float tot = 0.f;
#pragma unroll
            for (int i = 0; i < 8; i++) tot += sm[i];
            float mean = tot * (1.0f / 67108864.0f);
            float m = fmaxf(mean, 1e-5f);
            float s_w = __fdiv_rn(1.0f, m);
            float wdeq = __fdiv_rn(1.0f, s_w);
            g_wdeq = wdeq;
            g_thresh = 0.5f * wdeq;
            g_doneP = 0u;
        }
    }
}

// ---------------- kernel 3: GEMV on 2-bit codes with DP4A ----------------
// Block = 8 warps; warp handles 2 full rows; lanes span k (one g64 per lane per ss).
// Codes: LDG.128 coalesced. x int8 in smem, 132-word pitch per g64 (conflict-free).
__global__ void __launch_bounds__(256, 3) gemv2_kernel() {
    extern __shared__ unsigned xs[];
    int tid = threadIdx.x, lane = tid & 31, warp = tid >> 5;

    // fill smem (padded pitch 132 words per g64)
#pragma unroll
    for (int i = tid; i < 4096; i += 256) {
        uint4 v = ((const uint4*)g_xs)[i];
        int g64 = i >> 5, off4 = i & 31;
        *(uint4*)(xs + g64 * 132 + off4 * 4) = v;
    }
    __syncthreads();

    int rA = blockIdx.x * 16 + warp * 2;
    int rB = rA + 1;
    float fpA[8], fpB[8];
#pragma unroll
    for (int n = 0; n < 8; n++) { fpA[n] = 0.f; fpB[n] = 0.f; }

    const unsigned CTL0 = 0x40, CTL1 = 0x51, CTL2 = 0x62, CTL3 = 0x73;
    const unsigned LUT = 0xFF000100u;

#pragma unroll
    for (int ss = 0; ss < 4; ss++) {
        int g64 = ss * 32 + lane;
        uint4 cwA = *(const uint4*)(g_code + (size_t)rA * 2048 + g64 * 16);
        uint4 cwB = *(const uint4*)(g_code + (size_t)rB * 2048 + g64 * 16);
        float4 sc0 = *(const float4*)(g_sc + g64 * 8);
        float4 sc1 = *(const float4*)(g_sc + g64 * 8 + 4);
        int iA[8], iB[8];
#pragma unroll
        for (int n = 0; n < 8; n++) { iA[n] = 0; iB[n] = 0; }

        const unsigned* xb = xs + g64 * 132;
        unsigned wordsA[4] = {cwA.x, cwA.y, cwA.z, cwA.w};
        unsigned wordsB[4] = {cwB.x, cwB.y, cwB.z, cwB.w};
#pragma unroll
        for (int w4 = 0; w4 < 4; w4++) {
            unsigned wa = wordsA[w4], wb = wordsB[w4];
            unsigned loA = wa & 0x33333333u, hiA = (wa >> 2) & 0x33333333u;
            unsigned loB = wb & 0x33333333u, hiB = (wb >> 2) & 0x33333333u;
#pragma unroll
            for (int j = 0; j < 4; j++) {
                unsigned ctl = (j == 0) ? CTL0 : (j == 1) ? CTL1 : (j == 2) ? CTL2 : CTL3;
                unsigned qA = __byte_perm(LUT, 0u, __byte_perm(loA, hiA, ctl));
                unsigned qB = __byte_perm(LUT, 0u, __byte_perm(loB, hiB, ctl));
                const unsigned* xw = xb + (w4 * 4 + j) * 8;
                uint4 x0 = *(const uint4*)(xw);
                uint4 x1 = *(const uint4*)(xw + 4);
                iA[0] = __dp4a((int)qA, (int)x0.x, iA[0]);
                iA[1] = __dp4a((int)qA, (int)x0.y, iA[1]);
                iA[2] = __dp4a((int)qA, (int)x0.z, iA[2]);
                iA[3] = __dp4a((int)qA, (int)x0.w, iA[3]);
                iA[4] = __dp4a((int)qA, (int)x1.x, iA[4]);
                iA[5] = __dp4a((int)qA, (int)x1.y, iA[5]);
                iA[6] = __dp4a((int)qA, (int)x1.z, iA[6]);
                iA[7] = __dp4a((int)qA, (int)x1.w, iA[7]);
                iB[0] = __dp4a((int)qB, (int)x0.x, iB[0]);
                iB[1] = __dp4a((int)qB, (int)x0.y, iB[1]);
                iB[2] = __dp4a((int)qB, (int)x0.z, iB[2]);
                iB[3] = __dp4a((int)qB, (int)x0.w, iB[3]);
                iB[4] = __dp4a((int)qB, (int)x1.x, iB[4]);
                iB[5] = __dp4a((int)qB, (int)x1.y, iB[5]);
                iB[6] = __dp4a((int)qB, (int)x1.z, iB[6]);
                iB[7] = __dp4a((int)qB, (int)x1.w, iB[7]);
            }
        }
        float scv[8] = {sc0.x, sc0.y, sc0.z, sc0.w, sc1.x, sc1.y, sc1.z, sc1.w};
#pragma unroll
        for (int n = 0; n < 8; n++) {
            fpA[n] = fmaf((float)iA[n], scv[n], fpA[n]);
            fpB[n] = fmaf((float)iB[n], scv[n], fpB[n]);
        }
    }

    // cross-lane reduce (k partials) and write
#pragma unroll
    for (int n = 0; n < 8; n++) {
#pragma unroll
        for (int off = 16; off; off >>= 1) {
            fpA[n] += __shfl_xor_sync(0xffffffffu, fpA[n], off);
            fpB[n] += __shfl_xor_sync(0xffffffffu, fpB[n], off);
        }
    }
    if (lane == 0) {
#pragma unroll
        for (int n = 0; n < 8; n++) {
            g_part2[rA * 8 + n] = fpA[n];
            g_part2[rB * 8 + n] = fpB[n];
        }
    }
}

// ---------------- kernel 4: replay band entries against exact threshold ----------------
__global__ void correction_kernel() {
    unsigned cnt = g_bandcnt;
    if (cnt > BAND_CAP) cnt = BAND_CAP;
    float th = g_thresh;
    for (unsigned i = blockIdx.x * 256 + threadIdx.x; i < cnt; i += 256 * 256) {
        uint2 e = g_band[i];
        float w = __uint_as_float(e.y);
        if (fabsf(w) > th) {
            float sgn = copysignf(1.0f, w);
            unsigned idx = e.x;
            int m = idx >> 13, k = idx & 8191;
            float4 x0 = g_xt4[k * 2], x1 = g_xt4[k * 2 + 1];
            float* c = g_corr + m * 8;
            atomicAdd(c + 0, sgn * x0.x);
            atomicAdd(c + 1, sgn * x0.y);
            atomicAdd(c + 2, sgn * x0.z);
            atomicAdd(c + 3, sgn * x0.w);
            atomicAdd(c + 4, sgn * x1.x);
            atomicAdd(c + 5, sgn * x1.y);
            atomicAdd(c + 6, sgn * x1.z);
            atomicAdd(c + 7, sgn * x1.w);
        }
    }
}

// ---------------- kernel 5: merge + scale + transpose out ----------------
__global__ void finalize_out_kernel(float* __restrict__ out) {
    int gid = blockIdx.x * blockDim.x + threadIdx.x;   // 0..16383
    int m = gid >> 1, h = gid & 1;
    float4 P = *(const float4*)(g_part2 + m * 8 + h * 4);
    float4 C = *(const float4*)(g_corr + m * 8 + h * 4);
    float wd = g_wdeq;
    int n0 = h * 4;
    out[(n0 + 0) * M_DIM + m] = wd * (P.x + C.x);
    out[(n0 + 1) * M_DIM + m] = wd * (P.y + C.y);
    out[(n0 + 2) * M_DIM + m] = wd * (P.z + C.z);
    out[(n0 + 3) * M_DIM + m] = wd * (P.w + C.w);
}

// ---------------- launch ----------------
extern "C" void kernel_launch(void* const* d_in, const int* in_sizes, int n_in,
                              void* d_out, int out_size) {
    const float* x = (const float*)d_in[0];    // [8, 8192]
    const float* W = (const float*)d_in[1];    // [8192, 8192]
    float* out = (float*)d_out;                // [8, 8192]

    static bool attr_done = false;
    if (!attr_done) {
        cudaFuncSetAttribute(gemv2_kernel, cudaFuncAttributeMaxDynamicSharedMemorySize,
                             GEMV2_SMEM);
        attr_done = true;
    }

    sample_kernel<<<256, 256>>>((const float4*)W);     // t-hat -> band bounds
    prep_kernel<<<1152, 256>>>(x, (const float4*)W);   // ONE W pass: sums+codes+band+quant
    gemv2_kernel<<<512, 256, GEMV2_SMEM>>>();          // dp4a GEMV on codes
    correction_kernel<<<256, 256>>>();                 // band replay @ exact threshold
    finalize_out_kernel<<<64, 256>>>(out);             // merge + scale
}